// round 6
// baseline (speedup 1.0000x reference)
#include <cuda_runtime.h>
#include <cstdint>
#include <math.h>

// Problem constants
#define BATCH 16
#define DIMC  512
#define NPTS  4096

// ---------------------------------------------------------------------------
// Scratch (device globals — only legal scratch).
// hi/lo arrays store tf32-rounded values as floats (exact tf32 bit patterns).
// ---------------------------------------------------------------------------
__device__ float g_xhi [BATCH * DIMC * NPTS];
__device__ float g_xlo [BATCH * DIMC * NPTS];
__device__ float g_xThi[BATCH * DIMC * NPTS];
__device__ float g_xTlo[BATCH * DIMC * NPTS];
__device__ float g_Wqhi[DIMC * DIMC];
__device__ float g_Wqlo[DIMC * DIMC];
__device__ float g_Wkhi[DIMC * DIMC];
__device__ float g_Wklo[DIMC * DIMC];
__device__ float g_WvThi[DIMC * DIMC];
__device__ float g_WvTlo[DIMC * DIMC];
__device__ float g_Ghi[BATCH * DIMC * DIMC];
__device__ float g_Glo[BATCH * DIMC * DIMC];
__device__ float g_Thi[BATCH * DIMC * DIMC];
__device__ float g_Tlo[BATCH * DIMC * DIMC];
__device__ float g_S  [BATCH * DIMC * DIMC];
__device__ float g_Shi[BATCH * DIMC * DIMC];
__device__ float g_Slo[BATCH * DIMC * DIMC];
__device__ float g_Mhi[BATCH * DIMC * DIMC];
__device__ float g_Mlo[BATCH * DIMC * DIMC];

// ===========================================================================
// Helpers
// ===========================================================================
__device__ __forceinline__ uint32_t f2tf32(float x) {
    uint32_t r;
    asm("cvt.rna.tf32.f32 %0, %1;" : "=r"(r) : "f"(x));
    return r;
}

__device__ __forceinline__ void tf32_split(float v, float& hi, float& lo) {
    uint32_t h = f2tf32(v);
    hi = __uint_as_float(h);
    lo = __uint_as_float(f2tf32(v - hi));
}

#define CP_ASYNC16(saddr, gptr) \
    asm volatile("cp.async.cg.shared.global [%0], [%1], 16;" \
        :: "r"(saddr), "l"(gptr) : "memory")
#define CP_COMMIT()  asm volatile("cp.async.commit_group;" ::: "memory")
#define CP_WAIT(n)   asm volatile("cp.async.wait_group %0;" :: "n"(n) : "memory")

__device__ __forceinline__ uint32_t smem_u32(const void* p) {
    uint32_t a;
    asm("{ .reg .u64 t; cvta.to.shared.u64 t, %1; cvt.u32.u64 %0, t; }"
        : "=r"(a) : "l"(p));
    return a;
}

__device__ __forceinline__ void mma_tf32(
    float c[4], uint32_t a0, uint32_t a1, uint32_t a2, uint32_t a3,
    uint32_t b0, uint32_t b1)
{
    asm volatile(
        "mma.sync.aligned.m16n8k8.row.col.f32.tf32.tf32.f32 "
        "{%0,%1,%2,%3}, {%4,%5,%6,%7}, {%8,%9}, {%0,%1,%2,%3};"
        : "+f"(c[0]), "+f"(c[1]), "+f"(c[2]), "+f"(c[3])
        : "r"(a0), "r"(a1), "r"(a2), "r"(a3), "r"(b0), "r"(b1));
}

// ===========================================================================
// 3xTF32 NT GEMM on PRE-SPLIT operands.
//   C[m][n] = alpha * sum_k A[m][k]*B[n][k],  A = Ah+Al, B = Bh+Bl (tf32 pairs)
//   acc += Al*Bh + Ah*Bl + Ah*Bh  (error ~2^-22)
// Epilogue: writes plain C (if Cp) and/or split Ch/Cl (if Ch).
// CTA tile 128x128, BK=32, 8 warps 2(m)x4(n), warp tile 64x32.
// 3-stage cp.async pipeline, 1 syncthreads per k-tile.
// ===========================================================================
#define BM 128
#define BN 128
#define BKF 32
#define LDS_ROW 36
#define TILE_FLOATS (128 * LDS_ROW)          // 4608 floats (18432 B) per tile
#define STAGE_FLOATS (4 * TILE_FLOATS)       // Ah, Al, Bh, Bl
#define NSTAGE 3
#define SMEM_FLOATS (NSTAGE * STAGE_FLOATS)
#define SMEM_BYTES (SMEM_FLOATS * 4)         // 221184

__global__ __launch_bounds__(256) void gemm3_nt(
    const float* __restrict__ Ah, const float* __restrict__ Al,
    const float* __restrict__ Bh, const float* __restrict__ Bl,
    float* __restrict__ Cp, float* __restrict__ Ch, float* __restrict__ Cl,
    int K, int lda, int ldb, int ldc,
    long long strideA, long long strideB, long long strideC, float alpha)
{
    extern __shared__ float smem[];
    const int tid  = threadIdx.x;
    const int wid  = tid >> 5;
    const int lane = tid & 31;
    const int wm   = wid & 1;
    const int wn   = wid >> 1;

    const long long offA = blockIdx.z * strideA + (long long)(blockIdx.y * BM) * lda;
    const long long offB = blockIdx.z * strideB + (long long)(blockIdx.x * BN) * ldb;
    Ah += offA; Al += offA;
    Bh += offB; Bl += offB;
    const long long offC = blockIdx.z * strideC;

    const uint32_t smem_base = smem_u32(smem);

    float acc[4][4][4];
#pragma unroll
    for (int i = 0; i < 4; i++)
#pragma unroll
        for (int j = 0; j < 4; j++)
#pragma unroll
            for (int r = 0; r < 4; r++) acc[i][j][r] = 0.0f;

    const int ktiles = K / BKF;

    // Issue one k-tile: 4 operand tiles, 1024 16B chunks each -> 16 per thread.
    auto issue_tile = [&](int kt, int st) {
        const int kbase = kt * BKF;
        const uint32_t s0 = smem_base + (uint32_t)(st * STAGE_FLOATS) * 4u;
        const uint32_t tbytes = (uint32_t)TILE_FLOATS * 4u;
#pragma unroll
        for (int p = 0; p < 4; ++p) {
            const int c   = tid + p * 256;
            const int row = c >> 3;
            const int q   = c & 7;
            const uint32_t soff = (uint32_t)(row * LDS_ROW + q * 4) * 4u;
            const long long ga = (long long)row * lda + kbase + q * 4;
            const long long gb = (long long)row * ldb + kbase + q * 4;
            CP_ASYNC16(s0 + soff,              Ah + ga);
            CP_ASYNC16(s0 + tbytes + soff,     Al + ga);
            CP_ASYNC16(s0 + 2 * tbytes + soff, Bh + gb);
            CP_ASYNC16(s0 + 3 * tbytes + soff, Bl + gb);
        }
        CP_COMMIT();
    };

    issue_tile(0, 0);
    if (ktiles > 1) issue_tile(1, 1);

    const int gid = lane >> 2;
    const int tig = lane & 3;

    for (int kt = 0; kt < ktiles; ++kt) {
        const int st = kt % NSTAGE;
        if (kt == ktiles - 1) { CP_WAIT(0); } else { CP_WAIT(1); }
        __syncthreads();   // all warps done with stage (kt-1)%3; issue below is safe
        if (kt + 2 < ktiles) issue_tile(kt + 2, (kt + 2) % NSTAGE);

        const float* Ash = smem + st * STAGE_FLOATS;
        const float* Asl = Ash + TILE_FLOATS;
        const float* Bsh = Asl + TILE_FLOATS;
        const float* Bsl = Bsh + TILE_FLOATS;

#pragma unroll
        for (int s = 0; s < 4; ++s) {
            const int kk = s * 8 + tig;
            uint32_t ah[4][4], al[4][4];
#pragma unroll
            for (int fi = 0; fi < 4; ++fi) {
                const int r = wm * 64 + fi * 16 + gid;
                const float* ph = Ash + r * LDS_ROW + kk;
                const float* pl = Asl + r * LDS_ROW + kk;
                ah[fi][0] = __float_as_uint(ph[0]);
                ah[fi][1] = __float_as_uint(ph[8 * LDS_ROW]);
                ah[fi][2] = __float_as_uint(ph[4]);
                ah[fi][3] = __float_as_uint(ph[8 * LDS_ROW + 4]);
                al[fi][0] = __float_as_uint(pl[0]);
                al[fi][1] = __float_as_uint(pl[8 * LDS_ROW]);
                al[fi][2] = __float_as_uint(pl[4]);
                al[fi][3] = __float_as_uint(pl[8 * LDS_ROW + 4]);
            }
            uint32_t bh[4][2], bl[4][2];
#pragma unroll
            for (int fj = 0; fj < 4; ++fj) {
                const int n = wn * 32 + fj * 8 + gid;
                const float* ph = Bsh + n * LDS_ROW + kk;
                const float* pl = Bsl + n * LDS_ROW + kk;
                bh[fj][0] = __float_as_uint(ph[0]);
                bh[fj][1] = __float_as_uint(ph[4]);
                bl[fj][0] = __float_as_uint(pl[0]);
                bl[fj][1] = __float_as_uint(pl[4]);
            }
#pragma unroll
            for (int fi = 0; fi < 4; ++fi)
#pragma unroll
                for (int fj = 0; fj < 4; ++fj) {
                    mma_tf32(acc[fi][fj], al[fi][0], al[fi][1], al[fi][2], al[fi][3],
                             bh[fj][0], bh[fj][1]);
                    mma_tf32(acc[fi][fj], ah[fi][0], ah[fi][1], ah[fi][2], ah[fi][3],
                             bl[fj][0], bl[fj][1]);
                    mma_tf32(acc[fi][fj], ah[fi][0], ah[fi][1], ah[fi][2], ah[fi][3],
                             bh[fj][0], bh[fj][1]);
                }
        }
    }

    // Epilogue
    const int crow0 = blockIdx.y * BM + wm * 64 + gid;
    const int ccol0 = blockIdx.x * BN + wn * 32 + 2 * tig;
#pragma unroll
    for (int fi = 0; fi < 4; ++fi) {
#pragma unroll
        for (int fj = 0; fj < 4; ++fj) {
            const long long e0 = offC + (long long)(crow0 + fi * 16) * ldc + ccol0 + fj * 8;
            const long long e1 = e0 + 8 * ldc;
            float v0 = acc[fi][fj][0] * alpha, v1 = acc[fi][fj][1] * alpha;
            float v2 = acc[fi][fj][2] * alpha, v3 = acc[fi][fj][3] * alpha;
            if (Cp) {
                *(float2*)(Cp + e0) = make_float2(v0, v1);
                *(float2*)(Cp + e1) = make_float2(v2, v3);
            }
            if (Ch) {
                float h0, l0, h1, l1, h2, l2, h3, l3;
                tf32_split(v0, h0, l0); tf32_split(v1, h1, l1);
                tf32_split(v2, h2, l2); tf32_split(v3, h3, l3);
                *(float2*)(Ch + e0) = make_float2(h0, h1);
                *(float2*)(Ch + e1) = make_float2(h2, h3);
                *(float2*)(Cl + e0) = make_float2(l0, l1);
                *(float2*)(Cl + e1) = make_float2(l2, l3);
            }
        }
    }
}

// ===========================================================================
// Split (+optional transpose) kernel: per 32x32 tile.
//   oh/ol:   hi/lo in input layout (nullable)
//   oth/otl: hi/lo transposed     (nullable)
// ===========================================================================
__global__ __launch_bounds__(256) void split_kernel(
    const float* __restrict__ in,
    float* __restrict__ oh,  float* __restrict__ ol,
    float* __restrict__ oth, float* __restrict__ otl,
    int rows, int cols, long long sin, long long so, long long soT)
{
    __shared__ float th[32][33], tl[32][33];
    const float* I = in + (long long)blockIdx.z * sin;
    const int c0 = blockIdx.x * 32;
    const int r0 = blockIdx.y * 32;
    const int tx = threadIdx.x & 31, ty = threadIdx.x >> 5;   // 32 x 8

#pragma unroll
    for (int i = ty; i < 32; i += 8) {
        const float v = I[(long long)(r0 + i) * cols + c0 + tx];
        float hi, lo;
        tf32_split(v, hi, lo);
        if (oh) {
            const long long e = (long long)blockIdx.z * so + (long long)(r0 + i) * cols + c0 + tx;
            oh[e] = hi; ol[e] = lo;
        }
        th[i][tx] = hi; tl[i][tx] = lo;
    }
    if (oth) {
        __syncthreads();
#pragma unroll
        for (int i = ty; i < 32; i += 8) {
            const long long e = (long long)blockIdx.z * soT + (long long)(c0 + i) * rows + r0 + tx;
            oth[e] = th[tx][i];
            otl[e] = tl[tx][i];
        }
    }
}

// ===========================================================================
// Row softmax over S, writing SPLIT output Shi/Slo.
// ===========================================================================
__global__ __launch_bounds__(256) void softmax_split_kernel(
    const float* __restrict__ S, float* __restrict__ Shi, float* __restrict__ Slo)
{
    __shared__ float red[8];
    const long long row = blockIdx.x;
    const float* p = S + row * DIMC;
    const int t = threadIdx.x;
    const int lane = t & 31, warp = t >> 5;

    float v0 = p[t];
    float v1 = p[t + 256];

    float m = fmaxf(v0, v1);
#pragma unroll
    for (int o = 16; o; o >>= 1) m = fmaxf(m, __shfl_xor_sync(0xFFFFFFFFu, m, o));
    if (lane == 0) red[warp] = m;
    __syncthreads();
    m = red[0];
#pragma unroll
    for (int w = 1; w < 8; ++w) m = fmaxf(m, red[w]);
    __syncthreads();

    const float e0 = expf(v0 - m);
    const float e1 = expf(v1 - m);
    float sum = e0 + e1;
#pragma unroll
    for (int o = 16; o; o >>= 1) sum += __shfl_xor_sync(0xFFFFFFFFu, sum, o);
    if (lane == 0) red[warp] = sum;
    __syncthreads();
    sum = red[0];
#pragma unroll
    for (int w = 1; w < 8; ++w) sum += red[w];
    const float inv = 1.0f / sum;

    float h, l;
    tf32_split(e0 * inv, h, l);
    Shi[row * DIMC + t] = h;       Slo[row * DIMC + t] = l;
    tf32_split(e1 * inv, h, l);
    Shi[row * DIMC + t + 256] = h; Slo[row * DIMC + t + 256] = l;
}

// ===========================================================================
// Launch chain (all GEMMs NT, pre-split 3xTF32):
//   split x -> xhi/xlo + xThi/xTlo; split Wq, Wk; split+T Wv
//   G = x.x^T (K=4096)          -> Ghi/Glo
//   T = Wq.G (G symmetric)      -> Thi/Tlo
//   S = (1/tau) T.Wk^T          -> S plain
//   softmax(S)                  -> Shi/Slo
//   M = A.Wv (via WvT)          -> Mhi/Mlo
//   out = M.x (via xT)          -> out plain
// ===========================================================================
extern "C" void kernel_launch(void* const* d_in, const int* in_sizes, int n_in,
                              void* d_out, int out_size)
{
    const float* x  = (const float*)d_in[0];
    const float* Wq = (const float*)d_in[1];
    const float* Wk = (const float*)d_in[2];
    const float* Wv = (const float*)d_in[3];
    float* out = (float*)d_out;

    float *xhi, *xlo, *xThi, *xTlo;
    float *Wqhi, *Wqlo, *Wkhi, *Wklo, *WvThi, *WvTlo;
    float *Ghi, *Glo, *Thi, *Tlo, *S, *Shi, *Slo, *Mhi, *Mlo;
    cudaGetSymbolAddress((void**)&xhi,  g_xhi);
    cudaGetSymbolAddress((void**)&xlo,  g_xlo);
    cudaGetSymbolAddress((void**)&xThi, g_xThi);
    cudaGetSymbolAddress((void**)&xTlo, g_xTlo);
    cudaGetSymbolAddress((void**)&Wqhi, g_Wqhi);
    cudaGetSymbolAddress((void**)&Wqlo, g_Wqlo);
    cudaGetSymbolAddress((void**)&Wkhi, g_Wkhi);
    cudaGetSymbolAddress((void**)&Wklo, g_Wklo);
    cudaGetSymbolAddress((void**)&WvThi, g_WvThi);
    cudaGetSymbolAddress((void**)&WvTlo, g_WvTlo);
    cudaGetSymbolAddress((void**)&Ghi, g_Ghi);
    cudaGetSymbolAddress((void**)&Glo, g_Glo);
    cudaGetSymbolAddress((void**)&Thi, g_Thi);
    cudaGetSymbolAddress((void**)&Tlo, g_Tlo);
    cudaGetSymbolAddress((void**)&S,   g_S);
    cudaGetSymbolAddress((void**)&Shi, g_Shi);
    cudaGetSymbolAddress((void**)&Slo, g_Slo);
    cudaGetSymbolAddress((void**)&Mhi, g_Mhi);
    cudaGetSymbolAddress((void**)&Mlo, g_Mlo);

    cudaFuncSetAttribute(gemm3_nt,
                         cudaFuncAttributeMaxDynamicSharedMemorySize, SMEM_BYTES);

    const long long sXB = (long long)DIMC * NPTS;
    const long long sDD = (long long)DIMC * DIMC;
    const float inv_tau = (float)(1.0 / sqrt((double)DIMC));

    // Splits
    {
        dim3 gx(NPTS / 32, DIMC / 32, BATCH);
        split_kernel<<<gx, 256>>>(x, xhi, xlo, xThi, xTlo, DIMC, NPTS, sXB, sXB, sXB);
        dim3 gw(DIMC / 32, DIMC / 32, 1);
        split_kernel<<<gw, 256>>>(Wq, Wqhi, Wqlo, nullptr, nullptr, DIMC, DIMC, 0, 0, 0);
        split_kernel<<<gw, 256>>>(Wk, Wkhi, Wklo, nullptr, nullptr, DIMC, DIMC, 0, 0, 0);
        split_kernel<<<gw, 256>>>(Wv, nullptr, nullptr, WvThi, WvTlo, DIMC, DIMC, 0, 0, 0);
    }

    dim3 gSq(DIMC / BN, DIMC / BM, BATCH);   // 4 x 4 x 16
    dim3 gOut(NPTS / BN, DIMC / BM, BATCH);  // 32 x 4 x 16

    // G[b] = x[b] . x[b]^T  -> split
    gemm3_nt<<<gSq, 256, SMEM_BYTES>>>(xhi, xlo, xhi, xlo,
        nullptr, Ghi, Glo,
        NPTS, NPTS, NPTS, DIMC, sXB, sXB, sDD, 1.0f);

    // T[b] = Wq . G[b]  (G symmetric) -> split
    gemm3_nt<<<gSq, 256, SMEM_BYTES>>>(Wqhi, Wqlo, Ghi, Glo,
        nullptr, Thi, Tlo,
        DIMC, DIMC, DIMC, DIMC, 0LL, sDD, sDD, 1.0f);

    // S[b] = (1/tau) T[b] . Wk^T -> plain
    gemm3_nt<<<gSq, 256, SMEM_BYTES>>>(Thi, Tlo, Wkhi, Wklo,
        S, nullptr, nullptr,
        DIMC, DIMC, DIMC, DIMC, sDD, 0LL, sDD, inv_tau);

    // softmax -> split
    softmax_split_kernel<<<BATCH * DIMC, 256>>>(S, Shi, Slo);

    // M[b] = A[b] . Wv (B = WvT) -> split
    gemm3_nt<<<gSq, 256, SMEM_BYTES>>>(Shi, Slo, WvThi, WvTlo,
        nullptr, Mhi, Mlo,
        DIMC, DIMC, DIMC, DIMC, sDD, 0LL, sDD, 1.0f);

    // out[b] = M[b] . x[b]  (B = xT) -> plain
    gemm3_nt<<<gOut, 256, SMEM_BYTES>>>(Mhi, Mlo, xThi, xTlo,
        out, nullptr, nullptr,
        DIMC, DIMC, DIMC, NPTS, sDD, sXB, sXB, 1.0f);
}